// round 1
// baseline (speedup 1.0000x reference)
#include <cuda_runtime.h>

// Fisher-Kolmogorov explicit Euler rollout.
// u_{t+1} = u + active * dt * (D * lap6(u) + rho * u * (1-u)), 40 micro-steps,
// final clip to [0,1]. Grid [B=2][128][128][128] fp32, Dirichlet-0 boundaries.

#define W       128
#define BATCH   2
#define SUBSTEPS 10
#define MAX_DAYS 4
#define NSTEPS  (SUBSTEPS * MAX_DAYS)
#define MICRO_DT 0.1f

#define VOL ((size_t)W * W * W)

// Ping-pong scratch (allocation-free: __device__ globals).
__device__ float g_buf0[BATCH * VOL];
__device__ float g_buf1[BATCH * VOL];

__global__ __launch_bounds__(512)
void fk_step(const float* __restrict__ usrc,
             const float* __restrict__ Dm,
             const float* __restrict__ rm,
             float* __restrict__ udst,
             const int* __restrict__ dt_days,
             int day, int do_clip)
{
    // block = (32,4,4): 32 float4 lanes cover a full x-row of 128,
    // 4 y rows, 4 z planes. gridDim = (1, 32, 64): y tiles, z tiles x batch.
    const int x4 = threadIdx.x << 2;                       // 0..124
    const int y  = blockIdx.y * 4 + threadIdx.y;           // 0..127
    const int b  = blockIdx.z >> 5;                        // 0..1
    const int z  = (blockIdx.z & 31) * 4 + threadIdx.z;    // 0..127

    const size_t base = (((size_t)b * W + z) * W + y) * W + x4;

    const float4 c = *reinterpret_cast<const float4*>(usrc + base);
    float4 out;

    const bool active = (day < dt_days[b]);   // uniform per batch (per blockIdx.z)
    if (active) {
        const float left  = (x4 == 0)     ? 0.0f : __ldg(usrc + base - 1);
        const float right = (x4 == W - 4) ? 0.0f : __ldg(usrc + base + 4);

        float4 ym, yp, zm, zp;
        if (y == 0)      ym = make_float4(0.f, 0.f, 0.f, 0.f);
        else             ym = *reinterpret_cast<const float4*>(usrc + base - W);
        if (y == W - 1)  yp = make_float4(0.f, 0.f, 0.f, 0.f);
        else             yp = *reinterpret_cast<const float4*>(usrc + base + W);
        if (z == 0)      zm = make_float4(0.f, 0.f, 0.f, 0.f);
        else             zm = *reinterpret_cast<const float4*>(usrc + base - (size_t)W * W);
        if (z == W - 1)  zp = make_float4(0.f, 0.f, 0.f, 0.f);
        else             zp = *reinterpret_cast<const float4*>(usrc + base + (size_t)W * W);

        const float4 Dv = *reinterpret_cast<const float4*>(Dm + base);
        const float4 rv = *reinterpret_cast<const float4*>(rm + base);

        float4 lap;
        lap.x = left + c.y + ym.x + yp.x + zm.x + zp.x - 6.0f * c.x;
        lap.y = c.x  + c.z + ym.y + yp.y + zm.y + zp.y - 6.0f * c.y;
        lap.z = c.y  + c.w + ym.z + yp.z + zm.z + zp.z - 6.0f * c.z;
        lap.w = c.z  + right + ym.w + yp.w + zm.w + zp.w - 6.0f * c.w;

        out.x = c.x + MICRO_DT * (Dv.x * lap.x + rv.x * c.x * (1.0f - c.x));
        out.y = c.y + MICRO_DT * (Dv.y * lap.y + rv.y * c.y * (1.0f - c.y));
        out.z = c.z + MICRO_DT * (Dv.z * lap.z + rv.z * c.z * (1.0f - c.z));
        out.w = c.w + MICRO_DT * (Dv.w * lap.w + rv.w * c.w * (1.0f - c.w));
    } else {
        out = c;
    }

    if (do_clip) {
        out.x = fminf(fmaxf(out.x, 0.0f), 1.0f);
        out.y = fminf(fmaxf(out.y, 0.0f), 1.0f);
        out.z = fminf(fmaxf(out.z, 0.0f), 1.0f);
        out.w = fminf(fmaxf(out.w, 0.0f), 1.0f);
    }

    *reinterpret_cast<float4*>(udst + base) = out;
}

extern "C" void kernel_launch(void* const* d_in, const int* in_sizes, int n_in,
                              void* d_out, int out_size)
{
    const float* u_t0    = (const float*)d_in[0];
    const float* D_map   = (const float*)d_in[1];
    const float* rho_map = (const float*)d_in[2];
    const int*   dt_days = (const int*)  d_in[3];
    float*       out     = (float*)d_out;

    float *p0 = nullptr, *p1 = nullptr;
    cudaGetSymbolAddress((void**)&p0, g_buf0);
    cudaGetSymbolAddress((void**)&p1, g_buf1);

    dim3 block(32, 4, 4);
    dim3 grid(1, W / 4, (W / 4) * BATCH);

    // Ping-pong: step 0 reads u_t0, step NSTEPS-1 writes (clipped) to d_out.
    for (int s = 0; s < NSTEPS; ++s) {
        const float* src = (s == 0) ? u_t0 : ((s & 1) ? p0 : p1);
        float*       dst = (s == NSTEPS - 1) ? out : ((s & 1) ? p1 : p0);
        const int day = s / SUBSTEPS;
        const int clip = (s == NSTEPS - 1) ? 1 : 0;
        fk_step<<<grid, block>>>(src, D_map, rho_map, dst, dt_days, day, clip);
    }
    (void)in_sizes; (void)n_in; (void)out_size;
}

// round 2
// speedup vs baseline: 1.2716x; 1.2716x over previous
#include <cuda_runtime.h>

// Fisher-Kolmogorov explicit Euler rollout with inactive-step elision.
// Batch b is active only for steps s with (s/10) < dt_days[b] (a prefix of the
// 40 steps, always an even count). Inactive blocks exit with ~zero traffic.
// The batch's last active step writes clipped output directly to d_out.

#define W        128
#define BATCH    2
#define SUBSTEPS 10
#define MAX_DAYS 4
#define NSTEPS   (SUBSTEPS * MAX_DAYS)
#define MICRO_DT 0.1f

#define VOL ((size_t)W * W * W)

// Ping-pong scratch (allocation-free: __device__ globals).
__device__ float g_buf0[BATCH * VOL];
__device__ float g_buf1[BATCH * VOL];

__global__ __launch_bounds__(512)
void fk_step(const float* __restrict__ usrc,
             float* __restrict__ udst_buf,
             float* __restrict__ udst_out,
             const float* __restrict__ Dm,
             const float* __restrict__ rm,
             const int* __restrict__ dt_days,
             int day, int sub)
{
    const int b  = blockIdx.z >> 5;                        // 0..1
    const int dt = __ldg(dt_days + b);
    if (day >= dt) return;                                  // inactive: no work

    const bool finishing = (day == dt - 1) && (sub == SUBSTEPS - 1);

    const int x4 = threadIdx.x << 2;                       // 0..124
    const int y  = blockIdx.y * 4 + threadIdx.y;           // 0..127
    const int z  = (blockIdx.z & 31) * 4 + threadIdx.z;    // 0..127

    const size_t base = (((size_t)b * W + z) * W + y) * W + x4;

    const float4 c = *reinterpret_cast<const float4*>(usrc + base);

    const float left  = (x4 == 0)     ? 0.0f : __ldg(usrc + base - 1);
    const float right = (x4 == W - 4) ? 0.0f : __ldg(usrc + base + 4);

    float4 ym, yp, zm, zp;
    if (y == 0)      ym = make_float4(0.f, 0.f, 0.f, 0.f);
    else             ym = *reinterpret_cast<const float4*>(usrc + base - W);
    if (y == W - 1)  yp = make_float4(0.f, 0.f, 0.f, 0.f);
    else             yp = *reinterpret_cast<const float4*>(usrc + base + W);
    if (z == 0)      zm = make_float4(0.f, 0.f, 0.f, 0.f);
    else             zm = *reinterpret_cast<const float4*>(usrc + base - (size_t)W * W);
    if (z == W - 1)  zp = make_float4(0.f, 0.f, 0.f, 0.f);
    else             zp = *reinterpret_cast<const float4*>(usrc + base + (size_t)W * W);

    const float4 Dv = *reinterpret_cast<const float4*>(Dm + base);
    const float4 rv = *reinterpret_cast<const float4*>(rm + base);

    float4 lap;
    lap.x = left + c.y + ym.x + yp.x + zm.x + zp.x - 6.0f * c.x;
    lap.y = c.x  + c.z + ym.y + yp.y + zm.y + zp.y - 6.0f * c.y;
    lap.z = c.y  + c.w + ym.z + yp.z + zm.z + zp.z - 6.0f * c.z;
    lap.w = c.z  + right + ym.w + yp.w + zm.w + zp.w - 6.0f * c.w;

    float4 out;
    out.x = c.x + MICRO_DT * (Dv.x * lap.x + rv.x * c.x * (1.0f - c.x));
    out.y = c.y + MICRO_DT * (Dv.y * lap.y + rv.y * c.y * (1.0f - c.y));
    out.z = c.z + MICRO_DT * (Dv.z * lap.z + rv.z * c.z * (1.0f - c.z));
    out.w = c.w + MICRO_DT * (Dv.w * lap.w + rv.w * c.w * (1.0f - c.w));

    float* dst = udst_buf;
    if (finishing) {
        out.x = fminf(fmaxf(out.x, 0.0f), 1.0f);
        out.y = fminf(fmaxf(out.y, 0.0f), 1.0f);
        out.z = fminf(fmaxf(out.z, 0.0f), 1.0f);
        out.w = fminf(fmaxf(out.w, 0.0f), 1.0f);
        dst = udst_out;
    }

    *reinterpret_cast<float4*>(dst + base) = out;
}

// Handles dt_days[b] == 0 batches: clipped copy of u_t0 into d_out.
__global__ __launch_bounds__(512)
void fk_tail(const float* __restrict__ u0,
             float* __restrict__ out,
             const int* __restrict__ dt_days)
{
    const int b = blockIdx.z >> 5;
    if (__ldg(dt_days + b) != 0) return;

    const int x4 = threadIdx.x << 2;
    const int y  = blockIdx.y * 4 + threadIdx.y;
    const int z  = (blockIdx.z & 31) * 4 + threadIdx.z;
    const size_t base = (((size_t)b * W + z) * W + y) * W + x4;

    float4 v = *reinterpret_cast<const float4*>(u0 + base);
    v.x = fminf(fmaxf(v.x, 0.0f), 1.0f);
    v.y = fminf(fmaxf(v.y, 0.0f), 1.0f);
    v.z = fminf(fmaxf(v.z, 0.0f), 1.0f);
    v.w = fminf(fmaxf(v.w, 0.0f), 1.0f);
    *reinterpret_cast<float4*>(out + base) = v;
}

extern "C" void kernel_launch(void* const* d_in, const int* in_sizes, int n_in,
                              void* d_out, int out_size)
{
    const float* u_t0    = (const float*)d_in[0];
    const float* D_map   = (const float*)d_in[1];
    const float* rho_map = (const float*)d_in[2];
    const int*   dt_days = (const int*)  d_in[3];
    float*       out     = (float*)d_out;

    float *p0 = nullptr, *p1 = nullptr;
    cudaGetSymbolAddress((void**)&p0, g_buf0);
    cudaGetSymbolAddress((void**)&p1, g_buf1);
    float* bufs[2] = { p0, p1 };

    dim3 block(32, 4, 4);
    dim3 grid(1, W / 4, (W / 4) * BATCH);

    // Step s: reads (s==0 ? u_t0 : bufs[s&1]), writes bufs[(s+1)&1] — unless it
    // is the batch's finishing step, in which case it writes clipped d_out.
    for (int s = 0; s < NSTEPS; ++s) {
        const float* src = (s == 0) ? u_t0 : bufs[s & 1];
        float*       dst = bufs[(s + 1) & 1];
        fk_step<<<grid, block>>>(src, dst, out, D_map, rho_map, dt_days,
                                 s / SUBSTEPS, s % SUBSTEPS);
    }
    // dt==0 batches never wrote d_out: clipped copy of the input.
    fk_tail<<<grid, block>>>(u_t0, out, dt_days);

    (void)in_sizes; (void)n_in; (void)out_size;
}